// round 5
// baseline (speedup 1.0000x reference)
#include <cuda_runtime.h>
#include <cuda_bf16.h>

#define NN 100000
#define NE 3200000
#define NBLK ((NN + 255) / 256)   // 391 scan blocks

// Scratch (static __device__ allocations — allowed)
__device__ int   d_cnt[NN];        // in-degree counts (no self loop)
__device__ float d_dinv[NN];       // rsqrt(deg+1)
__device__ int   d_row[NE];
__device__ int   d_col[NE];
__device__ int   d_off[NN + 1];    // CSR offsets by col
__device__ int   d_cur[NN];        // fill cursors
__device__ int   d_bsum[NBLK];     // scan block sums
__device__ int   d_csr[NE];        // row ids sorted by col
__device__ float d_h1[NN * 32];

// ---------------------------------------------------------------------------
__global__ void k_zero(int n) {
    int i = blockIdx.x * blockDim.x + threadIdx.x;
    if (i < n) d_cnt[i] = 0;
}

// edge_index is INT32 (JAX x64-disabled downgrades jnp.int64): layout [2, E]
__global__ void k_deg(const int* __restrict__ ei, int E, int n) {
    int e = blockIdx.x * blockDim.x + threadIdx.x;
    if (e >= E) return;
    int r = ei[e];
    int c = ei[(size_t)E + e];
    if ((unsigned)r >= (unsigned)n) r = 0;
    if ((unsigned)c >= (unsigned)n) c = 0;
    d_row[e] = r;
    d_col[e] = c;
    atomicAdd(&d_cnt[c], 1);
}

__global__ void k_dinv(int n) {
    int i = blockIdx.x * blockDim.x + threadIdx.x;
    if (i < n) d_dinv[i] = rsqrtf((float)d_cnt[i] + 1.0f);
}

// ---- 3-kernel exclusive scan over d_cnt -> d_off ----
__global__ void k_scanA(int n) {
    __shared__ int s[256];
    int t = threadIdx.x;
    int i = blockIdx.x * 256 + t;
    int v = (i < n) ? d_cnt[i] : 0;
    s[t] = v;
    __syncthreads();
#pragma unroll
    for (int o = 1; o < 256; o <<= 1) {
        int a = (t >= o) ? s[t - o] : 0;
        __syncthreads();
        s[t] += a;
        __syncthreads();
    }
    if (i < n) d_off[i] = s[t] - v;          // exclusive within block
    if (t == 255) d_bsum[blockIdx.x] = s[255];
}

__global__ void k_scanB(int nb) {
    __shared__ int s[512];
    int t = threadIdx.x;
    int v = (t < nb) ? d_bsum[t] : 0;
    s[t] = v;
    __syncthreads();
#pragma unroll
    for (int o = 1; o < 512; o <<= 1) {
        int a = (t >= o) ? s[t - o] : 0;
        __syncthreads();
        s[t] += a;
        __syncthreads();
    }
    if (t < nb) d_bsum[t] = s[t] - v;        // exclusive block offsets
}

__global__ void k_scanC(int n, int E) {
    int i = blockIdx.x * blockDim.x + threadIdx.x;
    if (i < n) {
        int o = d_off[i] + d_bsum[i >> 8];
        d_off[i] = o;
        d_cur[i] = o;
    }
    if (i == 0) d_off[n] = E;
}

// counting-sort fill: csr[pos] = row, grouped by col
__global__ void k_fill(int E) {
    int e = blockIdx.x * blockDim.x + threadIdx.x;
    if (e >= E) return;
    int c = d_col[e];
    int p = atomicAdd(&d_cur[c], 1);
    d_csr[p] = d_row[e];
}

// ---------------------------------------------------------------------------
// Fused layer 1: per-node gather-aggregate (16 dims) + GEMV 16->32 + ReLU
// one warp per node; lanes split as 2 edge slots x 16 dims
__global__ void k_l1(const float* __restrict__ x,
                     const float* __restrict__ W1,
                     const float* __restrict__ b1, int n) {
    __shared__ float sW[16 * 32];
    __shared__ float sb[32];
    int tid = threadIdx.x;
    for (int j = tid; j < 512; j += blockDim.x) sW[j] = W1[j];
    if (tid < 32) sb[tid] = b1[tid];
    __syncthreads();

    int gw = (blockIdx.x * blockDim.x + tid) >> 5;
    int lane = tid & 31;
    if (gw >= n) return;

    int half = lane >> 4;
    int dim = lane & 15;
    int beg = d_off[gw], end = d_off[gw + 1];
    float dc = d_dinv[gw];

    float acc = 0.f;
    for (int i = beg + half; i < end; i += 2) {
        int r = d_csr[i];
        acc += d_dinv[r] * x[(size_t)r * 16 + dim];
    }
    acc += __shfl_xor_sync(0xffffffffu, acc, 16);   // fold edge slots
    // both halves now hold agg[dim]; add self loop, apply dc
    float v = dc * acc + dc * dc * x[(size_t)gw * 16 + dim];

    float o = sb[lane];
#pragma unroll
    for (int k = 0; k < 16; k++)
        o += __shfl_sync(0xffffffffu, v, k) * sW[k * 32 + lane];
    d_h1[(size_t)gw * 32 + lane] = fmaxf(o, 0.f);
}

// Fused layer 2 + MLP tail: gather-aggregate h1 (32 dims), GEMV W2+ReLU,
// GEMV Wl1+ReLU, dot Wl4 -> out.  one warp per node, lane = dim.
__global__ void k_l2(const float* __restrict__ W2, const float* __restrict__ b2,
                     const float* __restrict__ Wl1, const float* __restrict__ bl1,
                     const float* __restrict__ Wl4, const float* __restrict__ bl4,
                     float* __restrict__ out, int n) {
    __shared__ float sW2[1024];
    __shared__ float sWl1[1024];
    __shared__ float sb2[32], sbl1[32], sWl4[32];
    int tid = threadIdx.x;
    for (int j = tid; j < 1024; j += blockDim.x) {
        sW2[j] = W2[j];
        sWl1[j] = Wl1[j];
    }
    if (tid < 32) { sb2[tid] = b2[tid]; sbl1[tid] = bl1[tid]; sWl4[tid] = Wl4[tid]; }
    __syncthreads();

    int gw = (blockIdx.x * blockDim.x + tid) >> 5;
    int lane = tid & 31;
    if (gw >= n) return;

    int beg = d_off[gw], end = d_off[gw + 1];
    float dc = d_dinv[gw];

    float acc = 0.f;
    int i = beg;
    for (; i + 1 < end; i += 2) {
        int r0 = d_csr[i], r1 = d_csr[i + 1];
        float n0 = d_dinv[r0], n1 = d_dinv[r1];
        acc += n0 * d_h1[(size_t)r0 * 32 + lane];
        acc += n1 * d_h1[(size_t)r1 * 32 + lane];
    }
    if (i < end) {
        int r = d_csr[i];
        acc += d_dinv[r] * d_h1[(size_t)r * 32 + lane];
    }
    float v = dc * acc + dc * dc * d_h1[(size_t)gw * 32 + lane];

    float a2 = sb2[lane];
#pragma unroll
    for (int k = 0; k < 32; k++)
        a2 += __shfl_sync(0xffffffffu, v, k) * sW2[k * 32 + lane];
    float h2 = fmaxf(a2, 0.f);

    float a3 = sbl1[lane];
#pragma unroll
    for (int k = 0; k < 32; k++)
        a3 += __shfl_sync(0xffffffffu, h2, k) * sWl1[k * 32 + lane];
    float h3 = fmaxf(a3, 0.f);

    float p = h3 * sWl4[lane];
#pragma unroll
    for (int o = 16; o > 0; o >>= 1) p += __shfl_xor_sync(0xffffffffu, p, o);
    if (lane == 0) out[gw] = p + bl4[0];
}

// ---------------------------------------------------------------------------
extern "C" void kernel_launch(void* const* d_in, const int* in_sizes, int n_in,
                              void* d_out, int out_size) {
    // Runtime input resolution by element count (robust to metadata ordering).
    // Sizes: x=1600000 (f32), edge_index=6400000 (int32!), W1=512,
    //        W2=1024, Wl1=1024, b1=b2=bl1=Wl4=32, bl4=1.
    const float* x = 0; const int* ei = 0;
    const float *W1 = 0, *b1 = 0, *W2 = 0, *b2 = 0, *Wl1 = 0, *bl1 = 0, *Wl4 = 0, *bl4 = 0;

    bool alpha = (n_in > 0 && in_sizes[0] == 512);  // alphabetical puts W1 first
    int n1024 = 0, n32 = 0;
    for (int i = 0; i < n_in; i++) {
        int s = in_sizes[i];
        const void* p = d_in[i];
        if (s == 1600000)      x  = (const float*)p;
        else if (s == 6400000) ei = (const int*)p;
        else if (s == 512)     W1 = (const float*)p;
        else if (s == 1)       bl4 = (const float*)p;
        else if (s == 1024) {
            if (n1024 == 0) W2 = (const float*)p; else Wl1 = (const float*)p;
            n1024++;
        } else if (s == 32) {
            if (alpha) {
                if      (n32 == 0) Wl4 = (const float*)p;
                else if (n32 == 1) b1  = (const float*)p;
                else if (n32 == 2) b2  = (const float*)p;
                else               bl1 = (const float*)p;
            } else {
                if      (n32 == 0) b1  = (const float*)p;
                else if (n32 == 1) b2  = (const float*)p;
                else if (n32 == 2) bl1 = (const float*)p;
                else               Wl4 = (const float*)p;
            }
            n32++;
        }
    }
    float* out = (float*)d_out;

    int n = NN;
    int E = NE;

    const int TB = 256;
    int nodeBlocks = (n + TB - 1) / TB;
    int edgeBlocks = (E + TB - 1) / TB;
    int warpNodeBlocks = (n * 32 + TB - 1) / TB;

    k_zero<<<nodeBlocks, TB>>>(n);
    k_deg<<<edgeBlocks, TB>>>(ei, E, n);
    k_dinv<<<nodeBlocks, TB>>>(n);
    k_scanA<<<nodeBlocks, TB>>>(n);
    k_scanB<<<1, 512>>>(nodeBlocks);
    k_scanC<<<nodeBlocks, TB>>>(n, E);
    k_fill<<<edgeBlocks, TB>>>(E);
    k_l1<<<warpNodeBlocks, TB>>>(x, W1, b1, n);
    k_l2<<<warpNodeBlocks, TB>>>(W2, b2, Wl1, bl1, Wl4, bl4, out, n);
}

// round 6
// speedup vs baseline: 1.0802x; 1.0802x over previous
#include <cuda_runtime.h>
#include <cuda_bf16.h>

#define NN 100000
#define NE 3200000
#define NBLK ((NN + 255) / 256)   // 391 scan blocks

// Scratch (static __device__ allocations — allowed)
__device__ int   d_cnt[NN];        // in-degree counts (no self loop)
__device__ float d_dinv[NN];       // rsqrt(deg+1)
__device__ int   d_off[NN + 1];    // CSR offsets by col
__device__ int   d_cur[NN];        // fill cursors
__device__ int   d_bsum[NBLK];     // scan block sums
__device__ int   d_csr[NE];        // row ids sorted by col
__device__ float d_csrn[NE];       // dinv[row] per csr slot
__device__ float d_h1[NN * 32];

// ---------------------------------------------------------------------------
__global__ void k_zero(int n) {
    int i = blockIdx.x * blockDim.x + threadIdx.x;
    if (i < n) d_cnt[i] = 0;
}

// histogram of col (edge_index is int32, layout [2, E]; only col half needed)
__global__ void k_deg(const int* __restrict__ ei, int E, int n) {
    int e = blockIdx.x * blockDim.x + threadIdx.x;
    if (e >= E) return;
    int c = ei[(size_t)E + e];
    if ((unsigned)c >= (unsigned)n) c = 0;
    atomicAdd(&d_cnt[c], 1);
}

// ---- exclusive scan over d_cnt -> d_off (warp-shuffle version) + dinv ----
__global__ void k_scanA(int n) {
    __shared__ int ws[8];
    int t = threadIdx.x;
    int i = blockIdx.x * 256 + t;
    int lane = t & 31, w = t >> 5;
    int v = (i < n) ? d_cnt[i] : 0;
    int s = v;
#pragma unroll
    for (int o = 1; o < 32; o <<= 1) {
        int a = __shfl_up_sync(0xffffffffu, s, o);
        if (lane >= o) s += a;
    }
    if (lane == 31) ws[w] = s;
    __syncthreads();
    if (t < 8) {
        int a = ws[t];
#pragma unroll
        for (int o = 1; o < 8; o <<= 1) {
            int b = __shfl_up_sync(0xffu, a, o);
            if (t >= o) a += b;
        }
        ws[t] = a;
    }
    __syncthreads();
    int base = w ? ws[w - 1] : 0;
    int incl = base + s;
    if (i < n) {
        d_off[i] = incl - v;                 // exclusive within block
        d_dinv[i] = rsqrtf((float)v + 1.0f); // fused dinv
    }
    if (t == 255) d_bsum[blockIdx.x] = incl;
}

__global__ void k_scanB(int nb) {
    __shared__ int s[512];
    int t = threadIdx.x;
    int v = (t < nb) ? d_bsum[t] : 0;
    s[t] = v;
    __syncthreads();
#pragma unroll
    for (int o = 1; o < 512; o <<= 1) {
        int a = (t >= o) ? s[t - o] : 0;
        __syncthreads();
        s[t] += a;
        __syncthreads();
    }
    if (t < nb) d_bsum[t] = s[t] - v;        // exclusive block offsets
}

__global__ void k_scanC(int n, int E) {
    int i = blockIdx.x * blockDim.x + threadIdx.x;
    if (i < n) {
        int o = d_off[i] + d_bsum[i >> 8];
        d_off[i] = o;
        d_cur[i] = o;
    }
    if (i == 0) d_off[n] = E;
}

// counting-sort fill straight from edge_index: csr[pos]=row, csrn[pos]=dinv[row]
__global__ void k_fill(const int* __restrict__ ei, int E, int n) {
    int e = blockIdx.x * blockDim.x + threadIdx.x;
    if (e >= E) return;
    int r = ei[e];
    int c = ei[(size_t)E + e];
    if ((unsigned)r >= (unsigned)n) r = 0;
    if ((unsigned)c >= (unsigned)n) c = 0;
    int p = atomicAdd(&d_cur[c], 1);
    d_csr[p] = r;
    d_csrn[p] = d_dinv[r];
}

// ---------------------------------------------------------------------------
// Fused layer 1: gather-aggregate x (16 dims) via float4 + GEMV 16->32 + ReLU
// one warp per node; lane = (edge slot s = lane>>2) x (float4 chunk q = lane&3)
// -> 8 edges per loop step, LDG.128 feature loads
__global__ void k_l1(const float4* __restrict__ x4,
                     const float* __restrict__ x,
                     const float* __restrict__ W1,
                     const float* __restrict__ b1, int n) {
    __shared__ float sW[16 * 32];
    __shared__ float sb[32];
    int tid = threadIdx.x;
    for (int j = tid; j < 512; j += blockDim.x) sW[j] = W1[j];
    if (tid < 32) sb[tid] = b1[tid];
    __syncthreads();

    int gw = (blockIdx.x * blockDim.x + tid) >> 5;
    int lane = tid & 31;
    if (gw >= n) return;

    int s = lane >> 2;       // 8 edge slots
    int q = lane & 3;        // 4 float4 chunks = 16 dims
    int beg = d_off[gw], end = d_off[gw + 1];
    float dc = d_dinv[gw];

    float4 acc = make_float4(0.f, 0.f, 0.f, 0.f);
    for (int i = beg + s; i < end; i += 8) {
        int r = d_csr[i];
        float nm = d_csrn[i];
        float4 xv = x4[(size_t)r * 4 + q];
        acc.x += nm * xv.x; acc.y += nm * xv.y;
        acc.z += nm * xv.z; acc.w += nm * xv.w;
    }
    // fold edge slots (bits 2,3,4 of lane)
#pragma unroll
    for (int m = 4; m <= 16; m <<= 1) {
        acc.x += __shfl_xor_sync(0xffffffffu, acc.x, m);
        acc.y += __shfl_xor_sync(0xffffffffu, acc.y, m);
        acc.z += __shfl_xor_sync(0xffffffffu, acc.z, m);
        acc.w += __shfl_xor_sync(0xffffffffu, acc.w, m);
    }
    // redistribute: lane d (<16) takes comp d&3 of chunk d>>2 (held by lane d>>2)
    int src = lane >> 2;
    float c0 = __shfl_sync(0xffffffffu, acc.x, src);
    float c1 = __shfl_sync(0xffffffffu, acc.y, src);
    float c2 = __shfl_sync(0xffffffffu, acc.z, src);
    float c3 = __shfl_sync(0xffffffffu, acc.w, src);
    int cc = lane & 3;
    float agg = (cc == 0) ? c0 : (cc == 1) ? c1 : (cc == 2) ? c2 : c3;

    float v = 0.f;
    if (lane < 16)
        v = dc * agg + dc * dc * x[(size_t)gw * 16 + lane];

    float o = sb[lane];
#pragma unroll
    for (int k = 0; k < 16; k++)
        o += __shfl_sync(0xffffffffu, v, k) * sW[k * 32 + lane];
    d_h1[(size_t)gw * 32 + lane] = fmaxf(o, 0.f);
}

// Fused layer 2 + MLP tail: gather-aggregate h1 (32 dims) via float4,
// GEMV W2+ReLU, GEMV Wl1+ReLU, dot Wl4 -> out.  one warp per node.
// lane = (edge slot s = lane>>3) x (float4 chunk q = lane&7) -> 4 edges/step
__global__ void k_l2(const float* __restrict__ W2, const float* __restrict__ b2,
                     const float* __restrict__ Wl1, const float* __restrict__ bl1,
                     const float* __restrict__ Wl4, const float* __restrict__ bl4,
                     float* __restrict__ out, int n) {
    __shared__ float sW2[1024];
    __shared__ float sWl1[1024];
    __shared__ float sb2[32], sbl1[32], sWl4[32];
    int tid = threadIdx.x;
    for (int j = tid; j < 1024; j += blockDim.x) {
        sW2[j] = W2[j];
        sWl1[j] = Wl1[j];
    }
    if (tid < 32) { sb2[tid] = b2[tid]; sbl1[tid] = bl1[tid]; sWl4[tid] = Wl4[tid]; }
    __syncthreads();

    int gw = (blockIdx.x * blockDim.x + tid) >> 5;
    int lane = tid & 31;
    if (gw >= n) return;

    int s = lane >> 3;       // 4 edge slots
    int q = lane & 7;        // 8 float4 chunks = 32 dims
    int beg = d_off[gw], end = d_off[gw + 1];
    float dc = d_dinv[gw];
    const float4* h1f4 = (const float4*)d_h1;

    float4 acc = make_float4(0.f, 0.f, 0.f, 0.f);
    for (int i = beg + s; i < end; i += 4) {
        int r = d_csr[i];
        float nm = d_csrn[i];
        float4 hv = h1f4[(size_t)r * 8 + q];
        acc.x += nm * hv.x; acc.y += nm * hv.y;
        acc.z += nm * hv.z; acc.w += nm * hv.w;
    }
    // fold edge slots (bits 3,4)
#pragma unroll
    for (int m = 8; m <= 16; m <<= 1) {
        acc.x += __shfl_xor_sync(0xffffffffu, acc.x, m);
        acc.y += __shfl_xor_sync(0xffffffffu, acc.y, m);
        acc.z += __shfl_xor_sync(0xffffffffu, acc.z, m);
        acc.w += __shfl_xor_sync(0xffffffffu, acc.w, m);
    }
    // lane d takes comp d&3 of chunk d>>2 (held by lane d>>2, whose q = d>>2)
    int src = lane >> 2;
    float c0 = __shfl_sync(0xffffffffu, acc.x, src);
    float c1 = __shfl_sync(0xffffffffu, acc.y, src);
    float c2 = __shfl_sync(0xffffffffu, acc.z, src);
    float c3 = __shfl_sync(0xffffffffu, acc.w, src);
    int cc = lane & 3;
    float agg = (cc == 0) ? c0 : (cc == 1) ? c1 : (cc == 2) ? c2 : c3;

    float v = dc * agg + dc * dc * d_h1[(size_t)gw * 32 + lane];

    float a2 = sb2[lane];
#pragma unroll
    for (int k = 0; k < 32; k++)
        a2 += __shfl_sync(0xffffffffu, v, k) * sW2[k * 32 + lane];
    float h2 = fmaxf(a2, 0.f);

    float a3 = sbl1[lane];
#pragma unroll
    for (int k = 0; k < 32; k++)
        a3 += __shfl_sync(0xffffffffu, h2, k) * sWl1[k * 32 + lane];
    float h3 = fmaxf(a3, 0.f);

    float p = h3 * sWl4[lane];
#pragma unroll
    for (int o = 16; o > 0; o >>= 1) p += __shfl_xor_sync(0xffffffffu, p, o);
    if (lane == 0) out[gw] = p + bl4[0];
}

// ---------------------------------------------------------------------------
extern "C" void kernel_launch(void* const* d_in, const int* in_sizes, int n_in,
                              void* d_out, int out_size) {
    // Runtime input resolution by element count.
    // x=1600000 (f32), edge_index=6400000 (int32), W1=512, W2/Wl1=1024,
    // b1=b2=bl1=Wl4=32, bl4=1.
    const float* x = 0; const int* ei = 0;
    const float *W1 = 0, *b1 = 0, *W2 = 0, *b2 = 0, *Wl1 = 0, *bl1 = 0, *Wl4 = 0, *bl4 = 0;

    bool alpha = (n_in > 0 && in_sizes[0] == 512);  // alphabetical puts W1 first
    int n1024 = 0, n32 = 0;
    for (int i = 0; i < n_in; i++) {
        int s = in_sizes[i];
        const void* p = d_in[i];
        if (s == 1600000)      x  = (const float*)p;
        else if (s == 6400000) ei = (const int*)p;
        else if (s == 512)     W1 = (const float*)p;
        else if (s == 1)       bl4 = (const float*)p;
        else if (s == 1024) {
            if (n1024 == 0) W2 = (const float*)p; else Wl1 = (const float*)p;
            n1024++;
        } else if (s == 32) {
            if (alpha) {
                if      (n32 == 0) Wl4 = (const float*)p;
                else if (n32 == 1) b1  = (const float*)p;
                else if (n32 == 2) b2  = (const float*)p;
                else               bl1 = (const float*)p;
            } else {
                if      (n32 == 0) b1  = (const float*)p;
                else if (n32 == 1) b2  = (const float*)p;
                else if (n32 == 2) bl1 = (const float*)p;
                else               Wl4 = (const float*)p;
            }
            n32++;
        }
    }
    float* out = (float*)d_out;

    int n = NN;
    int E = NE;

    const int TB = 256;
    int nodeBlocks = (n + TB - 1) / TB;
    int edgeBlocks = (E + TB - 1) / TB;
    int warpNodeBlocks = (n * 32 + TB - 1) / TB;

    k_zero<<<nodeBlocks, TB>>>(n);
    k_deg<<<edgeBlocks, TB>>>(ei, E, n);
    k_scanA<<<nodeBlocks, TB>>>(n);
    k_scanB<<<1, 512>>>(nodeBlocks);
    k_scanC<<<nodeBlocks, TB>>>(n, E);
    k_fill<<<edgeBlocks, TB>>>(ei, E, n);
    k_l1<<<warpNodeBlocks, TB>>>((const float4*)x, x, W1, b1, n);
    k_l2<<<warpNodeBlocks, TB>>>(W2, b2, Wl1, bl1, Wl4, bl4, out, n);
}

// round 7
// speedup vs baseline: 1.0981x; 1.0165x over previous
#include <cuda_runtime.h>
#include <cuda_bf16.h>

#define NN 100000
#define NE 3200000
#define NBLK ((NN + 255) / 256)   // 391 scan blocks

// Scratch (static __device__ allocations — allowed)
__device__ int   d_cnt[NN];        // in-degree counts (no self loop)
__device__ float d_dinv[NN];       // rsqrt(deg+1)
__device__ int   d_off[NN + 1];    // CSR offsets by col
__device__ int   d_cur[NN];        // fill cursors
__device__ int   d_bsum[NBLK];     // scan block sums
__device__ int2  d_csr2[NE];       // {row, float_bits(dinv[row])} sorted by col
__device__ float d_h1[NN * 32];

// ---------------------------------------------------------------------------
// histogram of col; 4 edges per thread via int4
__global__ void k_deg(const int4* __restrict__ eic4, int E4, int n) {
    int e = blockIdx.x * blockDim.x + threadIdx.x;
    if (e >= E4) return;
    int4 c = eic4[e];
    if ((unsigned)c.x >= (unsigned)n) c.x = 0;
    if ((unsigned)c.y >= (unsigned)n) c.y = 0;
    if ((unsigned)c.z >= (unsigned)n) c.z = 0;
    if ((unsigned)c.w >= (unsigned)n) c.w = 0;
    atomicAdd(&d_cnt[c.x], 1);
    atomicAdd(&d_cnt[c.y], 1);
    atomicAdd(&d_cnt[c.z], 1);
    atomicAdd(&d_cnt[c.w], 1);
}

// ---- exclusive scan over d_cnt -> d_off (warp-shuffle) + fused dinv ----
__global__ void k_scanA(int n) {
    __shared__ int ws[8];
    int t = threadIdx.x;
    int i = blockIdx.x * 256 + t;
    int lane = t & 31, w = t >> 5;
    int v = (i < n) ? d_cnt[i] : 0;
    int s = v;
#pragma unroll
    for (int o = 1; o < 32; o <<= 1) {
        int a = __shfl_up_sync(0xffffffffu, s, o);
        if (lane >= o) s += a;
    }
    if (lane == 31) ws[w] = s;
    __syncthreads();
    if (t < 8) {
        int a = ws[t];
#pragma unroll
        for (int o = 1; o < 8; o <<= 1) {
            int b = __shfl_up_sync(0xffu, a, o);
            if (t >= o) a += b;
        }
        ws[t] = a;
    }
    __syncthreads();
    int base = w ? ws[w - 1] : 0;
    int incl = base + s;
    if (i < n) {
        d_off[i] = incl - v;                 // exclusive within block
        d_dinv[i] = rsqrtf((float)v + 1.0f); // fused dinv
    }
    if (t == 255) d_bsum[blockIdx.x] = incl;
}

// scan of 391 block sums: 512 threads = 16 warps, shuffle + smem
__global__ void k_scanB(int nb) {
    __shared__ int ws[16];
    int t = threadIdx.x;
    int lane = t & 31, w = t >> 5;
    int v = (t < nb) ? d_bsum[t] : 0;
    int s = v;
#pragma unroll
    for (int o = 1; o < 32; o <<= 1) {
        int a = __shfl_up_sync(0xffffffffu, s, o);
        if (lane >= o) s += a;
    }
    if (lane == 31) ws[w] = s;
    __syncthreads();
    if (t < 16) {
        int a = ws[t];
#pragma unroll
        for (int o = 1; o < 16; o <<= 1) {
            int b = __shfl_up_sync(0xffffu, a, o);
            if (t >= o) a += b;
        }
        ws[t] = a;
    }
    __syncthreads();
    int base = w ? ws[w - 1] : 0;
    if (t < nb) d_bsum[t] = base + s - v;    // exclusive block offsets
}

__global__ void k_scanC(int n, int E) {
    int i = blockIdx.x * blockDim.x + threadIdx.x;
    if (i < n) {
        int o = d_off[i] + d_bsum[i >> 8];
        d_off[i] = o;
        d_cur[i] = o;
    }
    if (i == 0) d_off[n] = E;
}

// counting-sort fill, 4 edges per thread; single packed 8B store per edge
__global__ void k_fill(const int4* __restrict__ eir4,
                       const int4* __restrict__ eic4, int E4, int n) {
    int e = blockIdx.x * blockDim.x + threadIdx.x;
    if (e >= E4) return;
    int4 r = eir4[e];
    int4 c = eic4[e];
    if ((unsigned)r.x >= (unsigned)n) r.x = 0;
    if ((unsigned)r.y >= (unsigned)n) r.y = 0;
    if ((unsigned)r.z >= (unsigned)n) r.z = 0;
    if ((unsigned)r.w >= (unsigned)n) r.w = 0;
    if ((unsigned)c.x >= (unsigned)n) c.x = 0;
    if ((unsigned)c.y >= (unsigned)n) c.y = 0;
    if ((unsigned)c.z >= (unsigned)n) c.z = 0;
    if ((unsigned)c.w >= (unsigned)n) c.w = 0;
    int p0 = atomicAdd(&d_cur[c.x], 1);
    int p1 = atomicAdd(&d_cur[c.y], 1);
    int p2 = atomicAdd(&d_cur[c.z], 1);
    int p3 = atomicAdd(&d_cur[c.w], 1);
    d_csr2[p0] = make_int2(r.x, __float_as_int(d_dinv[r.x]));
    d_csr2[p1] = make_int2(r.y, __float_as_int(d_dinv[r.y]));
    d_csr2[p2] = make_int2(r.z, __float_as_int(d_dinv[r.z]));
    d_csr2[p3] = make_int2(r.w, __float_as_int(d_dinv[r.w]));
}

// ---------------------------------------------------------------------------
// Fused layer 1: gather-aggregate x (16 dims) + GEMV 16->32 + ReLU
// warp/node; lane = (edge slot s = lane>>2) x (float4 chunk q = lane&3)
// software-pipelined 2 chains -> 16 edges in flight per warp
__global__ void k_l1(const float4* __restrict__ x4,
                     const float* __restrict__ x,
                     const float* __restrict__ W1,
                     const float* __restrict__ b1, int n) {
    __shared__ float sW[16 * 32];
    __shared__ float sb[32];
    int tid = threadIdx.x;
    for (int j = tid; j < 512; j += blockDim.x) sW[j] = W1[j];
    if (tid < 32) sb[tid] = b1[tid];
    __syncthreads();

    int gw = (blockIdx.x * blockDim.x + tid) >> 5;
    int lane = tid & 31;
    if (gw >= n) return;

    int s = lane >> 2;       // 8 edge slots
    int q = lane & 3;        // 4 float4 chunks = 16 dims
    int beg = d_off[gw], end = d_off[gw + 1];
    float dc = d_dinv[gw];

    float4 a0 = make_float4(0.f, 0.f, 0.f, 0.f);
    float4 a1 = make_float4(0.f, 0.f, 0.f, 0.f);
    int i = beg + s;
    for (; i + 8 < end; i += 16) {
        int2 e0 = d_csr2[i];
        int2 e1 = d_csr2[i + 8];
        float4 v0 = x4[(size_t)e0.x * 4 + q];
        float4 v1 = x4[(size_t)e1.x * 4 + q];
        float n0 = __int_as_float(e0.y), n1 = __int_as_float(e1.y);
        a0.x += n0 * v0.x; a0.y += n0 * v0.y; a0.z += n0 * v0.z; a0.w += n0 * v0.w;
        a1.x += n1 * v1.x; a1.y += n1 * v1.y; a1.z += n1 * v1.z; a1.w += n1 * v1.w;
    }
    if (i < end) {
        int2 e0 = d_csr2[i];
        float4 v0 = x4[(size_t)e0.x * 4 + q];
        float n0 = __int_as_float(e0.y);
        a0.x += n0 * v0.x; a0.y += n0 * v0.y; a0.z += n0 * v0.z; a0.w += n0 * v0.w;
    }
    float4 acc = make_float4(a0.x + a1.x, a0.y + a1.y, a0.z + a1.z, a0.w + a1.w);

    // fold edge slots (bits 2,3,4 of lane)
#pragma unroll
    for (int m = 4; m <= 16; m <<= 1) {
        acc.x += __shfl_xor_sync(0xffffffffu, acc.x, m);
        acc.y += __shfl_xor_sync(0xffffffffu, acc.y, m);
        acc.z += __shfl_xor_sync(0xffffffffu, acc.z, m);
        acc.w += __shfl_xor_sync(0xffffffffu, acc.w, m);
    }
    // redistribute: lane d (<16) takes comp d&3 of chunk d>>2
    int src = lane >> 2;
    float c0 = __shfl_sync(0xffffffffu, acc.x, src);
    float c1 = __shfl_sync(0xffffffffu, acc.y, src);
    float c2 = __shfl_sync(0xffffffffu, acc.z, src);
    float c3 = __shfl_sync(0xffffffffu, acc.w, src);
    int cc = lane & 3;
    float agg = (cc == 0) ? c0 : (cc == 1) ? c1 : (cc == 2) ? c2 : c3;

    float v = 0.f;
    if (lane < 16)
        v = dc * agg + dc * dc * x[(size_t)gw * 16 + lane];

    float o = sb[lane];
#pragma unroll
    for (int k = 0; k < 16; k++)
        o += __shfl_sync(0xffffffffu, v, k) * sW[k * 32 + lane];
    d_h1[(size_t)gw * 32 + lane] = fmaxf(o, 0.f);
}

// Fused layer 2 + MLP tail. warp/node; lane = (slot s = lane>>3) x (chunk q = lane&7)
// software-pipelined 2 chains -> 8 edges in flight per warp
__global__ void k_l2(const float* __restrict__ W2, const float* __restrict__ b2,
                     const float* __restrict__ Wl1, const float* __restrict__ bl1,
                     const float* __restrict__ Wl4, const float* __restrict__ bl4,
                     float* __restrict__ out, int n) {
    __shared__ float sW2[1024];
    __shared__ float sWl1[1024];
    __shared__ float sb2[32], sbl1[32], sWl4[32];
    int tid = threadIdx.x;
    for (int j = tid; j < 1024; j += blockDim.x) {
        sW2[j] = W2[j];
        sWl1[j] = Wl1[j];
    }
    if (tid < 32) { sb2[tid] = b2[tid]; sbl1[tid] = bl1[tid]; sWl4[tid] = Wl4[tid]; }
    __syncthreads();

    int gw = (blockIdx.x * blockDim.x + tid) >> 5;
    int lane = tid & 31;
    if (gw >= n) return;

    int s = lane >> 3;       // 4 edge slots
    int q = lane & 7;        // 8 float4 chunks = 32 dims
    int beg = d_off[gw], end = d_off[gw + 1];
    float dc = d_dinv[gw];
    const float4* h1f4 = (const float4*)d_h1;

    float4 a0 = make_float4(0.f, 0.f, 0.f, 0.f);
    float4 a1 = make_float4(0.f, 0.f, 0.f, 0.f);
    int i = beg + s;
    for (; i + 4 < end; i += 8) {
        int2 e0 = d_csr2[i];
        int2 e1 = d_csr2[i + 4];
        float4 v0 = h1f4[(size_t)e0.x * 8 + q];
        float4 v1 = h1f4[(size_t)e1.x * 8 + q];
        float n0 = __int_as_float(e0.y), n1 = __int_as_float(e1.y);
        a0.x += n0 * v0.x; a0.y += n0 * v0.y; a0.z += n0 * v0.z; a0.w += n0 * v0.w;
        a1.x += n1 * v1.x; a1.y += n1 * v1.y; a1.z += n1 * v1.z; a1.w += n1 * v1.w;
    }
    if (i < end) {
        int2 e0 = d_csr2[i];
        float4 v0 = h1f4[(size_t)e0.x * 8 + q];
        float n0 = __int_as_float(e0.y);
        a0.x += n0 * v0.x; a0.y += n0 * v0.y; a0.z += n0 * v0.z; a0.w += n0 * v0.w;
    }
    float4 acc = make_float4(a0.x + a1.x, a0.y + a1.y, a0.z + a1.z, a0.w + a1.w);

    // fold edge slots (bits 3,4)
#pragma unroll
    for (int m = 8; m <= 16; m <<= 1) {
        acc.x += __shfl_xor_sync(0xffffffffu, acc.x, m);
        acc.y += __shfl_xor_sync(0xffffffffu, acc.y, m);
        acc.z += __shfl_xor_sync(0xffffffffu, acc.z, m);
        acc.w += __shfl_xor_sync(0xffffffffu, acc.w, m);
    }
    // lane d takes comp d&3 of chunk d>>2
    int src = lane >> 2;
    float c0 = __shfl_sync(0xffffffffu, acc.x, src);
    float c1 = __shfl_sync(0xffffffffu, acc.y, src);
    float c2 = __shfl_sync(0xffffffffu, acc.z, src);
    float c3 = __shfl_sync(0xffffffffu, acc.w, src);
    int cc = lane & 3;
    float agg = (cc == 0) ? c0 : (cc == 1) ? c1 : (cc == 2) ? c2 : c3;

    float v = dc * agg + dc * dc * d_h1[(size_t)gw * 32 + lane];

    float a2 = sb2[lane];
#pragma unroll
    for (int k = 0; k < 32; k++)
        a2 += __shfl_sync(0xffffffffu, v, k) * sW2[k * 32 + lane];
    float h2 = fmaxf(a2, 0.f);

    float a3 = sbl1[lane];
#pragma unroll
    for (int k = 0; k < 32; k++)
        a3 += __shfl_sync(0xffffffffu, h2, k) * sWl1[k * 32 + lane];
    float h3 = fmaxf(a3, 0.f);

    float p = h3 * sWl4[lane];
#pragma unroll
    for (int o = 16; o > 0; o >>= 1) p += __shfl_xor_sync(0xffffffffu, p, o);
    if (lane == 0) out[gw] = p + bl4[0];
}

// ---------------------------------------------------------------------------
extern "C" void kernel_launch(void* const* d_in, const int* in_sizes, int n_in,
                              void* d_out, int out_size) {
    // Runtime input resolution by element count.
    const float* x = 0; const int* ei = 0;
    const float *W1 = 0, *b1 = 0, *W2 = 0, *b2 = 0, *Wl1 = 0, *bl1 = 0, *Wl4 = 0, *bl4 = 0;

    bool alpha = (n_in > 0 && in_sizes[0] == 512);  // alphabetical puts W1 first
    int n1024 = 0, n32 = 0;
    for (int i = 0; i < n_in; i++) {
        int s = in_sizes[i];
        const void* p = d_in[i];
        if (s == 1600000)      x  = (const float*)p;
        else if (s == 6400000) ei = (const int*)p;
        else if (s == 512)     W1 = (const float*)p;
        else if (s == 1)       bl4 = (const float*)p;
        else if (s == 1024) {
            if (n1024 == 0) W2 = (const float*)p; else Wl1 = (const float*)p;
            n1024++;
        } else if (s == 32) {
            if (alpha) {
                if      (n32 == 0) Wl4 = (const float*)p;
                else if (n32 == 1) b1  = (const float*)p;
                else if (n32 == 2) b2  = (const float*)p;
                else               bl1 = (const float*)p;
            } else {
                if      (n32 == 0) b1  = (const float*)p;
                else if (n32 == 1) b2  = (const float*)p;
                else if (n32 == 2) bl1 = (const float*)p;
                else               Wl4 = (const float*)p;
            }
            n32++;
        }
    }
    float* out = (float*)d_out;

    int n = NN;
    int E = NE;
    int E4 = E / 4;

    const int TB = 256;
    int nodeBlocks = (n + TB - 1) / TB;
    int e4Blocks = (E4 + TB - 1) / TB;
    int warpNodeBlocks = (n * 32 + TB - 1) / TB;

    void* cntPtr = 0;
    cudaGetSymbolAddress(&cntPtr, d_cnt);
    cudaMemsetAsync(cntPtr, 0, NN * sizeof(int), 0);

    const int4* eir4 = (const int4*)ei;             // rows half
    const int4* eic4 = (const int4*)(ei + E);       // cols half

    k_deg<<<e4Blocks, TB>>>(eic4, E4, n);
    k_scanA<<<nodeBlocks, TB>>>(n);
    k_scanB<<<1, 512>>>(NBLK);
    k_scanC<<<nodeBlocks, TB>>>(n, E);
    k_fill<<<e4Blocks, TB>>>(eir4, eic4, E4, n);
    k_l1<<<warpNodeBlocks, TB>>>((const float4*)x, x, W1, b1, n);
    k_l2<<<warpNodeBlocks, TB>>>(W2, b2, Wl1, bl1, Wl4, bl4, out, n);
}